// round 7
// baseline (speedup 1.0000x reference)
#include <cuda_runtime.h>
#include <cuda_fp16.h>
#include <cstdint>

#define FEAT 1184
#define BATCH 131072

// Pre-scaled fp16 weights: fp16(c*W)
__device__ __align__(16) __half g_wh[87040];

__global__ void prep_w(const float* __restrict__ w) {
    int i = blockIdx.x * 256 + threadIdx.x;
    if (i >= 87040) return;
    float c = (i < 65536) ? 0.0625f
            : (i < 81920) ? 0.08838834764831843f
            : (i < 86016) ? 0.125f
            : 0.17677669529663687f;
    g_wh[i] = __float2half_rn(w[i] * c);
}

static __device__ __forceinline__ uint32_t s2u(const void* p) {
    return (uint32_t)__cvta_generic_to_shared(p);
}
static __device__ __forceinline__ uint32_t sw128(uint32_t off) {
    return off ^ ((off >> 3) & 0x70);
}
static __device__ __forceinline__ uint32_t packh2(float a, float b) {
    __half2 h = __floats2half2_rn(a, b);
    return *(uint32_t*)&h;
}
static __device__ __forceinline__ void ldsm4(uint32_t* r, uint32_t addr) {
    asm volatile("ldmatrix.sync.aligned.m8n8.x4.shared.b16 {%0,%1,%2,%3}, [%4];"
                 : "=r"(r[0]), "=r"(r[1]), "=r"(r[2]), "=r"(r[3]) : "r"(addr));
}
static __device__ __forceinline__ void mma16816(float* c, const uint32_t* a,
                                                const uint32_t* b) {
    asm volatile("mma.sync.aligned.m16n8k16.row.col.f32.f16.f16.f32 "
                 "{%0,%1,%2,%3}, {%4,%5,%6,%7}, {%8,%9}, {%0,%1,%2,%3};"
                 : "+f"(c[0]), "+f"(c[1]), "+f"(c[2]), "+f"(c[3])
                 : "r"(a[0]), "r"(a[1]), "r"(a[2]), "r"(a[3]),
                   "r"(b[0]), "r"(b[1]));
}

// y[r, v] = sum_k A[r,k] * fp16(c*W[v,k]),  r = b*D + i,
//   A[r,k] = x[b*FEAT + xo + k*D + i]
template<int MUL, int D, int BN, int NT, int WNW>
__global__ void __launch_bounds__(NT, (NT == 256) ? 2 : 1) eqlin(
    const float* __restrict__ x, float* __restrict__ out,
    int xo, int wo, int mtiles)
{
    constexpr int KC      = (MUL < 64) ? MUL : 64;
    constexpr int NCH     = MUL / KC;
    constexpr int KSTEPS  = KC / 16;
    constexpr int OCTS    = KC / 8;
    constexpr int WSZ     = NCH * BN * 128;      // resident W bytes
    constexpr int A_OFF   = WSZ;
    // D>1: A buffer (16KB) aliased with OUT staging (128 x 36 fp32 = 18KB)
    constexpr int AREG    = (D == 1) ? 32768 : 18432;
    constexpr int STG_OFF = A_OFF + AREG;
    constexpr int NB      = 127 / D + 2;
    constexpr int STRIDE  = KC * D + 4;          // floats; == 4 (mod 32)
    constexpr int F4PB    = KC * D / 4;
    constexpr int STGSZ   = NB * STRIDE * 4;     // bytes per staging buffer
    constexpr int WARPS   = NT / 32;
    constexpr int WN      = BN / WNW;            // == 32 in all configs
    constexpr int NT8     = WN / 8;
    constexpr int MWARPS  = WARPS / WNW;
    constexpr int MT      = 128 / MWARPS / 16;
    constexpr int TASKS   = (128 * OCTS) / NT;
    constexpr int NPASS   = BN / 32;             // epilogue N-passes (D>1)

    extern __shared__ char smem[];
    const uint32_t sb = s2u(smem);
    float* outS = (float*)(smem + A_OFF);        // OUT staging (aliases A, D>1)
    const int tid  = threadIdx.x;
    const int lane = tid & 31;
    const int warp = tid >> 5;
    const int wm   = warp / WNW;
    const int wn   = warp % WNW;

    // ---- Resident W (fp16), chunk-major 128B rows, SW128 ----
    for (int e = tid; e < BN * (MUL / 8); e += NT) {
        int v = e / (MUL / 8), o = e % (MUL / 8);
        int k = o * 8;
        uint4 hv = *(const uint4*)(g_wh + wo + (size_t)v * MUL + k);
        uint32_t off = (uint32_t)((k / KC) * (BN * 128) + v * 128 + (k % KC) * 2);
        *(uint4*)(smem + sw128(off)) = hv;
    }

    float acc[MT][NT8][4];
    float st[(D == 1) ? 2 : 1][(D == 1) ? TASKS : 1][8];

    auto stage_ld = [&](int m, int c) {
        int b_lo = (m * 128) / D;
        for (int e = tid; e < NB * F4PB; e += NT) {
            int bl = e / F4PB, f = e - bl * F4PB;
            int b = b_lo + bl;
            if (b >= BATCH) b = BATCH - 1;
            const float* src = x + (size_t)b * FEAT + xo + c * (KC * D) + f * 4;
            uint32_t dst = sb + STG_OFF + (uint32_t)(bl * STRIDE + f * 4) * 4;
            asm volatile("cp.async.cg.shared.global [%0], [%1], 16;"
                         :: "r"(dst), "l"(src) : "memory");
        }
        asm volatile("cp.async.commit_group;" ::: "memory");
    };
    auto stage_ld2 = [&](int m, int c) {          // second staging buffer
        int b_lo = (m * 128) / D;
        for (int e = tid; e < NB * F4PB; e += NT) {
            int bl = e / F4PB, f = e - bl * F4PB;
            int b = b_lo + bl;
            if (b >= BATCH) b = BATCH - 1;
            const float* src = x + (size_t)b * FEAT + xo + c * (KC * D) + f * 4;
            uint32_t dst = sb + STG_OFF + STGSZ + (uint32_t)(bl * STRIDE + f * 4) * 4;
            asm volatile("cp.async.cg.shared.global [%0], [%1], 16;"
                         :: "r"(dst), "l"(src) : "memory");
        }
        asm volatile("cp.async.commit_group;" ::: "memory");
    };

    // D>1: strided LDS from staging buf -> fp16 -> swizzled A
    auto conv_chunk = [&](int m, int buf) {
        int b_lo = (m * 128) / D;
        const float* stgF = (const float*)(smem + STG_OFF + buf * STGSZ);
#pragma unroll
        for (int t = 0; t < TASKS; t++) {
            int e = tid + t * NT;
            int rl = e & 127, o = e >> 7;
            int r = m * 128 + rl;
            int b = r / D, bl = b - b_lo, i = r - b * D;
            const float* s = stgF + bl * STRIDE + (o * 8) * D + i;
            float v[8];
#pragma unroll
            for (int j = 0; j < 8; j++) v[j] = s[j * D];
            uint32_t p0 = packh2(v[0], v[1]), p1 = packh2(v[2], v[3]);
            uint32_t p2 = packh2(v[4], v[5]), p3 = packh2(v[6], v[7]);
            *(uint4*)(smem + A_OFF + sw128((uint32_t)(rl * 128 + o * 16))) =
                make_uint4(p0, p1, p2, p3);
        }
    };

    // D==1: coalesced LDG -> regs, then regs -> swizzled A
    auto ldg_chunk = [&](int slot, int m, int c) {
#pragma unroll
        for (int t = 0; t < TASKS; t++) {
            int e = tid + t * NT;
            int rl = e & 127, o = e >> 7;
            const float* xp = x + (size_t)(m * 128 + rl) * FEAT + xo + c * KC + o * 8;
            float4 q0 = *(const float4*)xp;
            float4 q1 = *(const float4*)(xp + 4);
            st[slot][t][0] = q0.x; st[slot][t][1] = q0.y;
            st[slot][t][2] = q0.z; st[slot][t][3] = q0.w;
            st[slot][t][4] = q1.x; st[slot][t][5] = q1.y;
            st[slot][t][6] = q1.z; st[slot][t][7] = q1.w;
        }
    };
    auto sts_chunk = [&](int slot, int buf) {
#pragma unroll
        for (int t = 0; t < TASKS; t++) {
            int e = tid + t * NT;
            int rl = e & 127, o = e >> 7;
            uint32_t p0 = packh2(st[slot][t][0], st[slot][t][1]);
            uint32_t p1 = packh2(st[slot][t][2], st[slot][t][3]);
            uint32_t p2 = packh2(st[slot][t][4], st[slot][t][5]);
            uint32_t p3 = packh2(st[slot][t][6], st[slot][t][7]);
            *(uint4*)(smem + A_OFF + buf * 16384 +
                      sw128((uint32_t)(rl * 128 + o * 16))) = make_uint4(p0, p1, p2, p3);
        }
    };

    auto mma_chunk = [&](uint32_t aoff, int c) {
        const int q = lane >> 3, p = lane & 7;
#pragma unroll
        for (int s = 0; s < KSTEPS; s++) {
            uint32_t af[MT][4];
#pragma unroll
            for (int mt = 0; mt < MT; mt++) {
                uint32_t row = (uint32_t)(wm * (MT * 16) + mt * 16 + (q & 1) * 8 + p);
                uint32_t kb  = (uint32_t)(s * 32 + (q >> 1) * 16);
                ldsm4(af[mt], sb + aoff + sw128(row * 128 + kb));
            }
#pragma unroll
            for (int ntp = 0; ntp < NT8 / 2; ntp++) {
                uint32_t vv = (uint32_t)(wn * WN + ntp * 16 + (q >> 1) * 8 + p);
                uint32_t kb = (uint32_t)(s * 32 + (q & 1) * 16);
                uint32_t bh[4];
                ldsm4(bh, sb + (uint32_t)(c * (BN * 128)) + sw128(vv * 128 + kb));
#pragma unroll
                for (int t2 = 0; t2 < 2; t2++)
#pragma unroll
                    for (int mt = 0; mt < MT; mt++)
                        mma16816(acc[mt][ntp * 2 + t2], af[mt], bh + 2 * t2);
            }
        }
    };

    if (D == 1) {
        ldg_chunk(0, blockIdx.x, 0);
        ldg_chunk(1, blockIdx.x, 1);
        __syncthreads();                       // W visible
        int g = 0;
        for (int m = blockIdx.x; m < mtiles; m += gridDim.x) {
#pragma unroll
            for (int mt = 0; mt < MT; mt++)
#pragma unroll
                for (int nt = 0; nt < NT8; nt++)
#pragma unroll
                    for (int j = 0; j < 4; j++) acc[mt][nt][j] = 0.0f;
#pragma unroll 1
            for (int c = 0; c < NCH; c++) {
                int slot = g & 1;
                sts_chunk(slot, slot);
                __syncthreads();
                int cn = c + 2, mn = m;
                while (cn >= NCH) { cn -= NCH; mn += gridDim.x; }
                if (mn < mtiles) ldg_chunk(slot, mn, cn);
                mma_chunk((uint32_t)(A_OFF + slot * 16384), c);
                g++;
            }
            // direct epilogue (contiguous float2 per row)
            const int row_base = m * 128 + wm * (MT * 16) + (lane >> 2);
            const int col_base = wn * WN + 2 * (lane & 3);
#pragma unroll
            for (int mt = 0; mt < MT; mt++)
#pragma unroll
                for (int nt = 0; nt < NT8; nt++) {
                    float* a = acc[mt][nt];
                    int cc = col_base + nt * 8;
                    int r1 = row_base + mt * 16;
                    *(float2*)(out + (size_t)r1 * FEAT + xo + cc) =
                        make_float2(a[0], a[1]);
                    *(float2*)(out + (size_t)(r1 + 8) * FEAT + xo + cc) =
                        make_float2(a[2], a[3]);
                }
        }
    } else {
        // stage cursor: chunk -> (ms, cs)
        int ms = blockIdx.x, cs = 0;
        auto stage_adv = [&](int which) {
            if (ms < mtiles) { if (which) stage_ld2(ms, cs); else stage_ld(ms, cs); }
            else asm volatile("cp.async.commit_group;" ::: "memory");
            if (++cs == NCH) { cs = 0; ms += gridDim.x; }
        };
        stage_adv(0);
        stage_adv(1);
        int g = 0;
        for (int m = blockIdx.x; m < mtiles; m += gridDim.x) {
#pragma unroll
            for (int mt = 0; mt < MT; mt++)
#pragma unroll
                for (int nt = 0; nt < NT8; nt++)
#pragma unroll
                    for (int j = 0; j < 4; j++) acc[mt][nt][j] = 0.0f;
#pragma unroll 1
            for (int c = 0; c < NCH; c++) {
                asm volatile("cp.async.wait_group 1;" ::: "memory");
                __syncthreads();               // staging visible; A/OUT free
                conv_chunk(m, g & 1);
                __syncthreads();               // A ready; staging buf reusable
                stage_adv(g & 1);              // chunk g+2 into same buf
                mma_chunk((uint32_t)A_OFF, c);
                g++;
            }
            // ---- staged epilogue: acc -> smem (pitch 36) -> contiguous STG
            const int b_lo = (m * 128) / D;
#pragma unroll 1
            for (int h = 0; h < NPASS; h++) {
                __syncthreads();               // mma done reading A / prior pass done
                if (wn == h) {
                    int rb = wm * (MT * 16) + (lane >> 2);
                    int cb = 2 * (lane & 3);
#pragma unroll
                    for (int mt = 0; mt < MT; mt++)
#pragma unroll
                        for (int nt = 0; nt < NT8; nt++) {
                            float* a = acc[mt][nt];
                            int row = rb + mt * 16, col = cb + nt * 8;
                            *(float2*)(outS + row * 36 + col) =
                                make_float2(a[0], a[1]);
                            *(float2*)(outS + (row + 8) * 36 + col) =
                                make_float2(a[2], a[3]);
                        }
                }
                __syncthreads();
                for (int e = tid; e < NB * 32 * D; e += NT) {
                    int bl = e / (32 * D), j = e - bl * (32 * D);
                    int b = b_lo + bl;
                    int i = j % D, vl = j / D;
                    int rl = b * D + i - m * 128;
                    if (rl >= 0 && rl < 128)
                        out[(size_t)b * FEAT + xo + h * (32 * D) + j] =
                            outS[rl * 36 + vl];
                }
            }
        }
    }
}

extern "C" void kernel_launch(void* const* d_in, const int* in_sizes, int n_in,
                              void* d_out, int out_size)
{
    const float* x = (const float*)d_in[0];
    const float* w = (const float*)d_in[1];
    float* out = (float*)d_out;

    prep_w<<<(87040 + 255) / 256, 256>>>(w);

    // smem budgets (mirror template math)
    constexpr int SM0 = 4 * 256 * 128 + 2 * 16384;              // 163840
    constexpr int SM1 = 2 * 128 * 128 + 18432 + 2 * 44 * 196 * 4; // 120192
    constexpr int SM2 = 64 * 128 + 18432 + 2 * 27 * 324 * 4;    // 96608
    constexpr int SM3 = 32 * 128 + 18432 + 2 * 20 * 228 * 4;    // 59008

    cudaFuncSetAttribute(eqlin<256, 1, 256, 512, 8>, cudaFuncAttributeMaxDynamicSharedMemorySize, SM0);
    cudaFuncSetAttribute(eqlin<128, 3, 128, 512, 4>, cudaFuncAttributeMaxDynamicSharedMemorySize, SM1);
    cudaFuncSetAttribute(eqlin<64, 5, 64, 256, 2>,   cudaFuncAttributeMaxDynamicSharedMemorySize, SM2);
    cudaFuncSetAttribute(eqlin<32, 7, 32, 256, 1>,   cudaFuncAttributeMaxDynamicSharedMemorySize, SM3);

    // block 0: mul=256, d=1: 1024 m-tiles, full N=256 in one CTA
    eqlin<256, 1, 256, 512, 8><<<148, 512, SM0>>>(x, out, 0, 0, 1024);
    // block 1: mul=128, d=3: 3072 m-tiles
    eqlin<128, 3, 128, 512, 4><<<148, 512, SM1>>>(x, out, 256, 65536, 3072);
    // block 2: mul=64, d=5: 5120 m-tiles (2 CTAs/SM)
    eqlin<64, 5, 64, 256, 2><<<296, 256, SM2>>>(x, out, 640, 81920, 5120);
    // block 3: mul=32, d=7: 7168 m-tiles (2 CTAs/SM)
    eqlin<32, 7, 32, 256, 1><<<296, 256, SM3>>>(x, out, 960, 86016, 7168);
}

// round 8
// speedup vs baseline: 1.4036x; 1.4036x over previous
#include <cuda_runtime.h>
#include <cuda_fp16.h>
#include <cstdint>

#define FEAT 1184
#define BATCH 131072

// Pre-scaled fp16 weights: fp16(c*W)
__device__ __align__(16) __half g_wh[87040];

__global__ void prep_w(const float* __restrict__ w) {
    int i = blockIdx.x * 256 + threadIdx.x;
    if (i >= 87040) return;
    float c = (i < 65536) ? 0.0625f
            : (i < 81920) ? 0.08838834764831843f
            : (i < 86016) ? 0.125f
            : 0.17677669529663687f;
    g_wh[i] = __float2half_rn(w[i] * c);
}

static __device__ __forceinline__ uint32_t s2u(const void* p) {
    return (uint32_t)__cvta_generic_to_shared(p);
}
static __device__ __forceinline__ uint32_t sw128(uint32_t off) {
    return off ^ ((off >> 3) & 0x70);
}
static __device__ __forceinline__ uint32_t packh2(float a, float b) {
    __half2 h = __floats2half2_rn(a, b);
    return *(uint32_t*)&h;
}
static __device__ __forceinline__ void ldsm4(uint32_t* r, uint32_t addr) {
    asm volatile("ldmatrix.sync.aligned.m8n8.x4.shared.b16 {%0,%1,%2,%3}, [%4];"
                 : "=r"(r[0]), "=r"(r[1]), "=r"(r[2]), "=r"(r[3]) : "r"(addr));
}
static __device__ __forceinline__ void mma16816(float* c, const uint32_t* a,
                                                const uint32_t* b) {
    asm volatile("mma.sync.aligned.m16n8k16.row.col.f32.f16.f16.f32 "
                 "{%0,%1,%2,%3}, {%4,%5,%6,%7}, {%8,%9}, {%0,%1,%2,%3};"
                 : "+f"(c[0]), "+f"(c[1]), "+f"(c[2]), "+f"(c[3])
                 : "r"(a[0]), "r"(a[1]), "r"(a[2]), "r"(a[3]),
                   "r"(b[0]), "r"(b[1]));
}

// y[r, v] = sum_k A[r,k] * fp16(c*W[v,k]),  r = b*D + i,
//   A[r,k] = x[b*FEAT + xo + k*D + i]
template<int MUL, int D, int BN, int NT, int WNW>
__global__ void __launch_bounds__(NT, (NT == 256) ? 2 : 1) eqlin(
    const float* __restrict__ x, float* __restrict__ out,
    int xo, int wo, int mtiles)
{
    constexpr int KC      = (MUL < 64) ? MUL : 64;
    constexpr int NCH     = MUL / KC;
    constexpr int KSTEPS  = KC / 16;
    constexpr int OCTS    = KC / 8;
    constexpr int WSZ     = NCH * BN * 128;      // resident W bytes
    constexpr int A_OFF   = WSZ;
    constexpr int NABUF   = (D == 1) ? 2 : 1;
    constexpr int STG_OFF = A_OFF + NABUF * 16384;
    constexpr int NB      = 127 / D + 2;         // batches touched per tile
    constexpr int STRIDE  = KC * D + 4;          // floats; == 4 (mod 32)
    constexpr int F4PB    = KC * D / 4;          // float4 per batch per chunk
    constexpr int STGSZ   = NB * STRIDE * 4;     // bytes per staging buffer
    constexpr int WARPS   = NT / 32;
    constexpr int WN      = BN / WNW;            // == 32 in all configs
    constexpr int NT8     = WN / 8;
    constexpr int MWARPS  = WARPS / WNW;
    constexpr int MT      = 128 / MWARPS / 16;   // m16 frags per warp
    constexpr int TASKS   = (128 * OCTS) / NT;

    extern __shared__ char smem[];
    const uint32_t sb = s2u(smem);
    const int tid  = threadIdx.x;
    const int lane = tid & 31;
    const int warp = tid >> 5;
    const int wm   = warp / WNW;
    const int wn   = warp % WNW;

    // ---- Resident W (fp16), chunk-major 128B rows, SW128 ----
    for (int e = tid; e < BN * (MUL / 8); e += NT) {
        int v = e / (MUL / 8), o = e % (MUL / 8);
        int k = o * 8;
        uint4 hv = *(const uint4*)(g_wh + wo + (size_t)v * MUL + k);
        uint32_t off = (uint32_t)((k / KC) * (BN * 128) + v * 128 + (k % KC) * 2);
        *(uint4*)(smem + sw128(off)) = hv;
    }

    float acc[MT][NT8][4];
    float st[(D == 1) ? TASKS : 1][8];

    // cp.async into staging buffer `buf`: contiguous float4 span of the chunk
    auto stage_ld = [&](int m, int c, int buf) {
        int b_lo = (m * 128) / D;
        for (int e = tid; e < NB * F4PB; e += NT) {
            int bl = e / F4PB, f = e - bl * F4PB;
            int b = b_lo + bl;
            if (b >= BATCH) b = BATCH - 1;
            const float* src = x + (size_t)b * FEAT + xo + c * (KC * D) + f * 4;
            uint32_t dst = sb + STG_OFF + (uint32_t)buf * STGSZ +
                           (uint32_t)(bl * STRIDE + f * 4) * 4;
            asm volatile("cp.async.cg.shared.global [%0], [%1], 16;"
                         :: "r"(dst), "l"(src) : "memory");
        }
        asm volatile("cp.async.commit_group;" ::: "memory");
    };

    // D>1: strided LDS from staging -> fp16 -> swizzled A
    auto conv_chunk = [&](int m, int buf) {
        int b_lo = (m * 128) / D;
        const float* stgF = (const float*)(smem + STG_OFF + buf * STGSZ);
#pragma unroll
        for (int t = 0; t < TASKS; t++) {
            int e = tid + t * NT;
            int rl = e & 127, o = e >> 7;
            int r = m * 128 + rl;
            int b = r / D, bl = b - b_lo, i = r - b * D;
            const float* s = stgF + bl * STRIDE + (o * 8) * D + i;
            float v[8];
#pragma unroll
            for (int j = 0; j < 8; j++) v[j] = s[j * D];
            uint32_t p0 = packh2(v[0], v[1]), p1 = packh2(v[2], v[3]);
            uint32_t p2 = packh2(v[4], v[5]), p3 = packh2(v[6], v[7]);
            *(uint4*)(smem + A_OFF + sw128((uint32_t)(rl * 128 + o * 16))) =
                make_uint4(p0, p1, p2, p3);
        }
    };

    // D==1: coalesced LDG float4 -> regs -> swizzled A
    auto ldg_chunk = [&](int m, int c) {
#pragma unroll
        for (int t = 0; t < TASKS; t++) {
            int e = tid + t * NT;
            int rl = e & 127, o = e >> 7;
            const float* xp = x + (size_t)(m * 128 + rl) * FEAT + xo + c * KC + o * 8;
            float4 q0 = *(const float4*)xp;
            float4 q1 = *(const float4*)(xp + 4);
            st[t][0] = q0.x; st[t][1] = q0.y; st[t][2] = q0.z; st[t][3] = q0.w;
            st[t][4] = q1.x; st[t][5] = q1.y; st[t][6] = q1.z; st[t][7] = q1.w;
        }
    };
    auto sts_chunk = [&](int buf) {
#pragma unroll
        for (int t = 0; t < TASKS; t++) {
            int e = tid + t * NT;
            int rl = e & 127, o = e >> 7;
            uint32_t p0 = packh2(st[t][0], st[t][1]), p1 = packh2(st[t][2], st[t][3]);
            uint32_t p2 = packh2(st[t][4], st[t][5]), p3 = packh2(st[t][6], st[t][7]);
            *(uint4*)(smem + A_OFF + buf * 16384 +
                      sw128((uint32_t)(rl * 128 + o * 16))) = make_uint4(p0, p1, p2, p3);
        }
    };

    auto mma_chunk = [&](uint32_t aoff, int c) {
        const int q = lane >> 3, p = lane & 7;
#pragma unroll
        for (int s = 0; s < KSTEPS; s++) {
            uint32_t af[MT][4];
#pragma unroll
            for (int mt = 0; mt < MT; mt++) {
                uint32_t row = (uint32_t)(wm * (MT * 16) + mt * 16 + (q & 1) * 8 + p);
                uint32_t kb  = (uint32_t)(s * 32 + (q >> 1) * 16);
                ldsm4(af[mt], sb + aoff + sw128(row * 128 + kb));
            }
#pragma unroll
            for (int ntp = 0; ntp < NT8 / 2; ntp++) {
                uint32_t vv = (uint32_t)(wn * WN + ntp * 16 + (q >> 1) * 8 + p);
                uint32_t kb = (uint32_t)(s * 32 + (q & 1) * 16);
                uint32_t bh[4];
                ldsm4(bh, sb + (uint32_t)(c * (BN * 128)) + sw128(vv * 128 + kb));
#pragma unroll
                for (int t2 = 0; t2 < 2; t2++)
#pragma unroll
                    for (int mt = 0; mt < MT; mt++)
                        mma16816(acc[mt][ntp * 2 + t2], af[mt], bh + 2 * t2);
            }
        }
    };

    auto epilogue = [&](int m) {
        const int row_base = m * 128 + wm * (MT * 16) + (lane >> 2);
        const int col_base = wn * WN + 2 * (lane & 3);
#pragma unroll
        for (int mt = 0; mt < MT; mt++) {
#pragma unroll
            for (int nt = 0; nt < NT8; nt++) {
                float* a = acc[mt][nt];
                int cc = col_base + nt * 8;
                int r1 = row_base + mt * 16, r2 = r1 + 8;
                if (D == 1) {
                    *(float2*)(out + (size_t)r1 * FEAT + xo + cc) =
                        make_float2(a[0], a[1]);
                    *(float2*)(out + (size_t)r2 * FEAT + xo + cc) =
                        make_float2(a[2], a[3]);
                } else {
                    int b1 = r1 / D, i1 = r1 - b1 * D;
                    int b2 = r2 / D, i2 = r2 - b2 * D;
                    float* o1 = out + (size_t)b1 * FEAT + xo + i1;
                    float* o2 = out + (size_t)b2 * FEAT + xo + i2;
                    o1[(size_t)cc * D]       = a[0];
                    o1[(size_t)(cc + 1) * D] = a[1];
                    o2[(size_t)cc * D]       = a[2];
                    o2[(size_t)(cc + 1) * D] = a[3];
                }
            }
        }
    };

    if (D == 1) {
        ldg_chunk(blockIdx.x, 0);
        __syncthreads();                       // W visible
        int g = 0;
        for (int m = blockIdx.x; m < mtiles; m += gridDim.x) {
#pragma unroll
            for (int mt = 0; mt < MT; mt++)
#pragma unroll
                for (int nt = 0; nt < NT8; nt++)
#pragma unroll
                    for (int j = 0; j < 4; j++) acc[mt][nt][j] = 0.0f;
#pragma unroll 1
            for (int c = 0; c < NCH; c++) {
                int buf = g & 1;
                sts_chunk(buf);
                __syncthreads();
                int cn = c + 1, mn = m;
                if (cn == NCH) { cn = 0; mn = m + gridDim.x; }
                if (mn < mtiles) ldg_chunk(mn, cn);
                mma_chunk((uint32_t)(A_OFF + buf * 16384), c);
                g++;
            }
            epilogue(m);
        }
    } else {
        // depth-2 staging pipeline: chunk cursor (ms, cs)
        int ms = blockIdx.x, cs = 0;
        auto stage_adv = [&](int buf) {
            if (ms < mtiles) stage_ld(ms, cs, buf);
            else asm volatile("cp.async.commit_group;" ::: "memory");
            if (++cs == NCH) { cs = 0; ms += gridDim.x; }
        };
        stage_adv(0);
        stage_adv(1);
        int g = 0;
        for (int m = blockIdx.x; m < mtiles; m += gridDim.x) {
#pragma unroll
            for (int mt = 0; mt < MT; mt++)
#pragma unroll
                for (int nt = 0; nt < NT8; nt++)
#pragma unroll
                    for (int j = 0; j < 4; j++) acc[mt][nt][j] = 0.0f;
#pragma unroll 1
            for (int c = 0; c < NCH; c++) {
                asm volatile("cp.async.wait_group 1;" ::: "memory");
                __syncthreads();               // staging g visible; A free
                conv_chunk(m, g & 1);
                __syncthreads();               // A ready; staging buf reusable
                stage_adv(g & 1);              // chunk g+2 into same buf
                mma_chunk((uint32_t)A_OFF, c);
                g++;
            }
            epilogue(m);
        }
    }
}

extern "C" void kernel_launch(void* const* d_in, const int* in_sizes, int n_in,
                              void* d_out, int out_size)
{
    const float* x = (const float*)d_in[0];
    const float* w = (const float*)d_in[1];
    float* out = (float*)d_out;

    prep_w<<<(87040 + 255) / 256, 256>>>(w);

    // smem budgets (mirror template math)
    constexpr int SM0 = 4 * 256 * 128 + 2 * 16384;                // 163840
    constexpr int SM1 = 2 * 128 * 128 + 16384 + 2 * 44 * 196 * 4; // 118144
    constexpr int SM2 = 64 * 128 + 16384 + 2 * 27 * 324 * 4;      // 94560
    constexpr int SM3 = 32 * 128 + 16384 + 2 * 20 * 228 * 4;      // 56960

    cudaFuncSetAttribute(eqlin<256, 1, 256, 512, 8>, cudaFuncAttributeMaxDynamicSharedMemorySize, SM0);
    cudaFuncSetAttribute(eqlin<128, 3, 128, 512, 4>, cudaFuncAttributeMaxDynamicSharedMemorySize, SM1);
    cudaFuncSetAttribute(eqlin<64, 5, 64, 256, 2>,   cudaFuncAttributeMaxDynamicSharedMemorySize, SM2);
    cudaFuncSetAttribute(eqlin<32, 7, 32, 256, 1>,   cudaFuncAttributeMaxDynamicSharedMemorySize, SM3);

    // block 0: mul=256, d=1: 1024 m-tiles, full N=256 in one CTA
    eqlin<256, 1, 256, 512, 8><<<148, 512, SM0>>>(x, out, 0, 0, 1024);
    // block 1: mul=128, d=3: 3072 m-tiles
    eqlin<128, 3, 128, 512, 4><<<148, 512, SM1>>>(x, out, 256, 65536, 3072);
    // block 2: mul=64, d=5: 5120 m-tiles (2 CTAs/SM)
    eqlin<64, 5, 64, 256, 2><<<296, 256, SM2>>>(x, out, 640, 81920, 5120);
    // block 3: mul=32, d=7: 7168 m-tiles (2 CTAs/SM)
    eqlin<32, 7, 32, 256, 1><<<296, 256, SM3>>>(x, out, 960, 86016, 7168);
}

// round 9
// speedup vs baseline: 1.4397x; 1.0257x over previous
#include <cuda_runtime.h>
#include <cuda_fp16.h>
#include <cstdint>

#define FEAT 1184
#define BATCH 131072

// Pre-scaled fp16 weights: fp16(c*W)
__device__ __align__(16) __half g_wh[87040];

__global__ void prep_w(const float* __restrict__ w) {
    int i = blockIdx.x * 256 + threadIdx.x;
    if (i >= 87040) return;
    float c = (i < 65536) ? 0.0625f
            : (i < 81920) ? 0.08838834764831843f
            : (i < 86016) ? 0.125f
            : 0.17677669529663687f;
    g_wh[i] = __float2half_rn(w[i] * c);
}

static __device__ __forceinline__ uint32_t s2u(const void* p) {
    return (uint32_t)__cvta_generic_to_shared(p);
}
static __device__ __forceinline__ uint32_t sw128(uint32_t off) {
    return off ^ ((off >> 3) & 0x70);
}
static __device__ __forceinline__ uint32_t packh2(float a, float b) {
    __half2 h = __floats2half2_rn(a, b);
    return *(uint32_t*)&h;
}
static __device__ __forceinline__ void ldsm4(uint32_t* r, uint32_t addr) {
    asm volatile("ldmatrix.sync.aligned.m8n8.x4.shared.b16 {%0,%1,%2,%3}, [%4];"
                 : "=r"(r[0]), "=r"(r[1]), "=r"(r[2]), "=r"(r[3]) : "r"(addr));
}
static __device__ __forceinline__ void mma16816(float* c, const uint32_t* a,
                                                const uint32_t* b) {
    asm volatile("mma.sync.aligned.m16n8k16.row.col.f32.f16.f16.f32 "
                 "{%0,%1,%2,%3}, {%4,%5,%6,%7}, {%8,%9}, {%0,%1,%2,%3};"
                 : "+f"(c[0]), "+f"(c[1]), "+f"(c[2]), "+f"(c[3])
                 : "r"(a[0]), "r"(a[1]), "r"(a[2]), "r"(a[3]),
                   "r"(b[0]), "r"(b[1]));
}

// y[r, v] = sum_k A[r,k] * fp16(c*W[v,k]),  r = b*D + i,
//   A[r,k] = x[b*FEAT + xo + k*D + i]
// D>1 tiles are batch-aligned: tile m covers batches [m*NBT, m*NBT+NBT),
// rows MROWS = NBT*D <= 128, MMA padded to 128 rows.
template<int MUL, int D, int BN, int NT, int WNW, int NBT, int OCC>
__global__ void __launch_bounds__(NT, OCC) eqlin(
    const float* __restrict__ x, float* __restrict__ out,
    int xo, int wo, int mtiles)
{
    constexpr int KC      = (MUL < 64) ? MUL : 64;
    constexpr int NCH     = MUL / KC;
    constexpr int KSTEPS  = KC / 16;
    constexpr int OCTS    = KC / 8;
    constexpr int WSZ     = NCH * BN * 128;      // resident W bytes
    constexpr int A_OFF   = WSZ;
    constexpr int NABUF   = (D == 1) ? 2 : 1;
    constexpr int STG_OFF = A_OFF + NABUF * 16384;
    constexpr int MROWS   = (D == 1) ? 128 : NBT * D;
    constexpr int STRIDE  = KC * D + 4;          // floats; == 4 (mod 32)
    constexpr int F4PB    = KC * D / 4;          // float4 per batch per chunk
    constexpr int STGSZ   = NBT * STRIDE * 4;    // bytes per staging buffer
    constexpr int NSBUF   = (NCH > 1) ? 2 : 1;   // staging depth
    constexpr int WARPS   = NT / 32;
    constexpr int WN      = BN / WNW;            // == 32 in all configs
    constexpr int NT8     = WN / 8;
    constexpr int MWARPS  = WARPS / WNW;
    constexpr int MT      = 128 / MWARPS / 16;   // m16 frags per warp
    constexpr int TASKS   = (128 * OCTS) / NT;

    extern __shared__ char smem[];
    const uint32_t sb = s2u(smem);
    const int tid  = threadIdx.x;
    const int lane = tid & 31;
    const int warp = tid >> 5;
    const int wm   = warp / WNW;
    const int wn   = warp % WNW;

    // ---- Resident W (fp16), chunk-major 128B rows, SW128 ----
    for (int e = tid; e < BN * (MUL / 8); e += NT) {
        int v = e / (MUL / 8), o = e % (MUL / 8);
        int k = o * 8;
        uint4 hv = *(const uint4*)(g_wh + wo + (size_t)v * MUL + k);
        uint32_t off = (uint32_t)((k / KC) * (BN * 128) + v * 128 + (k % KC) * 2);
        *(uint4*)(smem + sw128(off)) = hv;
    }

    float acc[MT][NT8][4];
    float st[(D == 1) ? TASKS : 1][8];

    // cp.async: contiguous float4 span of chunk c of tile m into buffer buf
    auto stage_ld = [&](int m, int c, int buf) {
        int B0 = m * NBT;
        for (int e = tid; e < NBT * F4PB; e += NT) {
            int bl = e / F4PB, f = e - bl * F4PB;
            int b = B0 + bl;
            if (b >= BATCH) b = BATCH - 1;
            const float* src = x + (size_t)b * FEAT + xo + c * (KC * D) + f * 4;
            uint32_t dst = sb + STG_OFF + (uint32_t)buf * STGSZ +
                           (uint32_t)(bl * STRIDE + f * 4) * 4;
            asm volatile("cp.async.cg.shared.global [%0], [%1], 16;"
                         :: "r"(dst), "l"(src) : "memory");
        }
        asm volatile("cp.async.commit_group;" ::: "memory");
    };

    // D>1: strided LDS from staging -> fp16 -> swizzled A (rows batch-local)
    auto conv_chunk = [&](int buf) {
        const float* stgF = (const float*)(smem + STG_OFF + buf * STGSZ);
#pragma unroll
        for (int t = 0; t < TASKS; t++) {
            int e = tid + t * NT;
            int rl = e & 127, o = e >> 7;
            int bl = rl / D;
            if (bl > NBT - 1) bl = NBT - 1;        // padding rows
            int i = rl - bl * D;
            const float* s = stgF + bl * STRIDE + (o * 8) * D + i;
            float v[8];
#pragma unroll
            for (int j = 0; j < 8; j++) v[j] = s[j * D];
            uint32_t p0 = packh2(v[0], v[1]), p1 = packh2(v[2], v[3]);
            uint32_t p2 = packh2(v[4], v[5]), p3 = packh2(v[6], v[7]);
            *(uint4*)(smem + A_OFF + sw128((uint32_t)(rl * 128 + o * 16))) =
                make_uint4(p0, p1, p2, p3);
        }
    };

    // D==1: coalesced LDG float4 -> regs -> swizzled A
    auto ldg_chunk = [&](int m, int c) {
#pragma unroll
        for (int t = 0; t < TASKS; t++) {
            int e = tid + t * NT;
            int rl = e & 127, o = e >> 7;
            const float* xp = x + (size_t)(m * 128 + rl) * FEAT + xo + c * KC + o * 8;
            float4 q0 = *(const float4*)xp;
            float4 q1 = *(const float4*)(xp + 4);
            st[t][0] = q0.x; st[t][1] = q0.y; st[t][2] = q0.z; st[t][3] = q0.w;
            st[t][4] = q1.x; st[t][5] = q1.y; st[t][6] = q1.z; st[t][7] = q1.w;
        }
    };
    auto sts_chunk = [&](int buf) {
#pragma unroll
        for (int t = 0; t < TASKS; t++) {
            int e = tid + t * NT;
            int rl = e & 127, o = e >> 7;
            uint32_t p0 = packh2(st[t][0], st[t][1]), p1 = packh2(st[t][2], st[t][3]);
            uint32_t p2 = packh2(st[t][4], st[t][5]), p3 = packh2(st[t][6], st[t][7]);
            *(uint4*)(smem + A_OFF + buf * 16384 +
                      sw128((uint32_t)(rl * 128 + o * 16))) = make_uint4(p0, p1, p2, p3);
        }
    };

    auto mma_chunk = [&](uint32_t aoff, int c) {
        const int q = lane >> 3, p = lane & 7;
#pragma unroll
        for (int s = 0; s < KSTEPS; s++) {
            uint32_t af[MT][4];
#pragma unroll
            for (int mt = 0; mt < MT; mt++) {
                uint32_t row = (uint32_t)(wm * (MT * 16) + mt * 16 + (q & 1) * 8 + p);
                uint32_t kb  = (uint32_t)(s * 32 + (q >> 1) * 16);
                ldsm4(af[mt], sb + aoff + sw128(row * 128 + kb));
            }
#pragma unroll
            for (int ntp = 0; ntp < NT8 / 2; ntp++) {
                uint32_t vv = (uint32_t)(wn * WN + ntp * 16 + (q >> 1) * 8 + p);
                uint32_t kb = (uint32_t)(s * 32 + (q & 1) * 16);
                uint32_t bh[4];
                ldsm4(bh, sb + (uint32_t)(c * (BN * 128)) + sw128(vv * 128 + kb));
#pragma unroll
                for (int t2 = 0; t2 < 2; t2++)
#pragma unroll
                    for (int mt = 0; mt < MT; mt++)
                        mma16816(acc[mt][ntp * 2 + t2], af[mt], bh + 2 * t2);
            }
        }
    };

    auto zero_acc = [&]() {
#pragma unroll
        for (int mt = 0; mt < MT; mt++)
#pragma unroll
            for (int nt = 0; nt < NT8; nt++)
#pragma unroll
                for (int j = 0; j < 4; j++) acc[mt][nt][j] = 0.0f;
    };

    if (D == 1) {
        ldg_chunk(blockIdx.x, 0);
        __syncthreads();                       // W visible
        int g = 0;
        for (int m = blockIdx.x; m < mtiles; m += gridDim.x) {
            zero_acc();
#pragma unroll 1
            for (int c = 0; c < NCH; c++) {
                int buf = g & 1;
                sts_chunk(buf);
                __syncthreads();
                int cn = c + 1, mn = m;
                if (cn == NCH) { cn = 0; mn = m + gridDim.x; }
                if (mn < mtiles) ldg_chunk(mn, cn);
                mma_chunk((uint32_t)(A_OFF + buf * 16384), c);
                g++;
            }
            // direct epilogue (contiguous float2 per row)
            const int row_base = m * 128 + wm * (MT * 16) + (lane >> 2);
            const int col_base = wn * WN + 2 * (lane & 3);
#pragma unroll
            for (int mt = 0; mt < MT; mt++)
#pragma unroll
                for (int nt = 0; nt < NT8; nt++) {
                    float* a = acc[mt][nt];
                    int cc = col_base + nt * 8;
                    int r1 = row_base + mt * 16;
                    *(float2*)(out + (size_t)r1 * FEAT + xo + cc) =
                        make_float2(a[0], a[1]);
                    *(float2*)(out + (size_t)(r1 + 8) * FEAT + xo + cc) =
                        make_float2(a[2], a[3]);
                }
        }
    } else if (NCH == 1) {
        // single chunk per tile; single staging buffer, overlap next-tile load
        if (blockIdx.x < mtiles) stage_ld(blockIdx.x, 0, 0);
        for (int m = blockIdx.x; m < mtiles; m += gridDim.x) {
            zero_acc();
            asm volatile("cp.async.wait_group 0;" ::: "memory");
            __syncthreads();                   // staging + W visible; A free
            conv_chunk(0);
            __syncthreads();                   // A ready; staging reusable
            int mn = m + gridDim.x;
            if (mn < mtiles) stage_ld(mn, 0, 0);   // overlaps MMA + epilogue
            mma_chunk((uint32_t)A_OFF, 0);
            // guarded direct epilogue (batch-aligned rows)
            const int B0 = m * NBT;
            const int row_base = wm * (MT * 16) + (lane >> 2);
            const int col_base = wn * WN + 2 * (lane & 3);
#pragma unroll
            for (int mt = 0; mt < MT; mt++) {
                int r1 = row_base + mt * 16, r2 = r1 + 8;
                int q1 = r1 / D, q2 = r2 / D;
                int b1 = B0 + q1, b2 = B0 + q2;
                float* o1 = out + (size_t)b1 * FEAT + xo + (r1 - q1 * D);
                float* o2 = out + (size_t)b2 * FEAT + xo + (r2 - q2 * D);
                bool g1 = (r1 < MROWS) && (b1 < BATCH);
                bool g2 = (r2 < MROWS) && (b2 < BATCH);
#pragma unroll
                for (int nt = 0; nt < NT8; nt++) {
                    float* a = acc[mt][nt];
                    int cc = col_base + nt * 8;
                    if (g1) { o1[(size_t)cc * D] = a[0];
                              o1[(size_t)(cc + 1) * D] = a[1]; }
                    if (g2) { o2[(size_t)cc * D] = a[2];
                              o2[(size_t)(cc + 1) * D] = a[3]; }
                }
            }
        }
    } else {
        // NCH==2 (block1): depth-2 staging pipeline across chunks
        int ms = blockIdx.x, cs = 0;
        auto stage_adv = [&](int buf) {
            if (ms < mtiles) stage_ld(ms, cs, buf);
            else asm volatile("cp.async.commit_group;" ::: "memory");
            if (++cs == NCH) { cs = 0; ms += gridDim.x; }
        };
        stage_adv(0);
        stage_adv(1);
        int g = 0;
        for (int m = blockIdx.x; m < mtiles; m += gridDim.x) {
            zero_acc();
#pragma unroll 1
            for (int c = 0; c < NCH; c++) {
                asm volatile("cp.async.wait_group 1;" ::: "memory");
                __syncthreads();               // staging g visible; A free
                conv_chunk(g & 1);
                __syncthreads();               // A ready; staging buf reusable
                stage_adv(g & 1);              // chunk g+2 into same buf
                mma_chunk((uint32_t)A_OFF, c);
                g++;
            }
            const int B0 = m * NBT;
            const int row_base = wm * (MT * 16) + (lane >> 2);
            const int col_base = wn * WN + 2 * (lane & 3);
#pragma unroll
            for (int mt = 0; mt < MT; mt++) {
                int r1 = row_base + mt * 16, r2 = r1 + 8;
                int q1 = r1 / D, q2 = r2 / D;
                int b1 = B0 + q1, b2 = B0 + q2;
                float* o1 = out + (size_t)b1 * FEAT + xo + (r1 - q1 * D);
                float* o2 = out + (size_t)b2 * FEAT + xo + (r2 - q2 * D);
                bool g1 = (r1 < MROWS) && (b1 < BATCH);
                bool g2 = (r2 < MROWS) && (b2 < BATCH);
#pragma unroll
                for (int nt = 0; nt < NT8; nt++) {
                    float* a = acc[mt][nt];
                    int cc = col_base + nt * 8;
                    if (g1) { o1[(size_t)cc * D] = a[0];
                              o1[(size_t)(cc + 1) * D] = a[1]; }
                    if (g2) { o2[(size_t)cc * D] = a[2];
                              o2[(size_t)(cc + 1) * D] = a[3]; }
                }
            }
        }
    }
}

extern "C" void kernel_launch(void* const* d_in, const int* in_sizes, int n_in,
                              void* d_out, int out_size)
{
    const float* x = (const float*)d_in[0];
    const float* w = (const float*)d_in[1];
    float* out = (float*)d_out;

    prep_w<<<(87040 + 255) / 256, 256>>>(w);

    // smem budgets (mirror template math)
    constexpr int SM0 = 4 * 256 * 128 + 2 * 16384;           // 163840
    constexpr int SM1 = 32768 + 16384 + 2 * (42 * 196 * 4);  // 115008
    constexpr int SM2 = 8192 + 16384 + (25 * 324 * 4);       // 56976
    constexpr int SM3 = 4096 + 16384 + (18 * 228 * 4);       // 36896

    cudaFuncSetAttribute(eqlin<256, 1, 256, 512, 8, 128, 1>, cudaFuncAttributeMaxDynamicSharedMemorySize, SM0);
    cudaFuncSetAttribute(eqlin<128, 3, 128, 512, 4, 42, 1>,  cudaFuncAttributeMaxDynamicSharedMemorySize, SM1);
    cudaFuncSetAttribute(eqlin<64, 5, 64, 256, 2, 25, 3>,    cudaFuncAttributeMaxDynamicSharedMemorySize, SM2);
    cudaFuncSetAttribute(eqlin<32, 7, 32, 256, 1, 18, 3>,    cudaFuncAttributeMaxDynamicSharedMemorySize, SM3);

    // block 0: mul=256, d=1: 1024 m-tiles, full N=256 in one CTA
    eqlin<256, 1, 256, 512, 8, 128, 1><<<148, 512, SM0>>>(x, out, 0, 0, 1024);
    // block 1: mul=128, d=3: 3121 tiles of 42 batches (126 rows)
    eqlin<128, 3, 128, 512, 4, 42, 1><<<148, 512, SM1>>>(x, out, 256, 65536, 3121);
    // block 2: mul=64, d=5: 5243 tiles of 25 batches (125 rows), 3 CTAs/SM
    eqlin<64, 5, 64, 256, 2, 25, 3><<<444, 256, SM2>>>(x, out, 640, 81920, 5243);
    // block 3: mul=32, d=7: 7282 tiles of 18 batches (126 rows), 3 CTAs/SM
    eqlin<32, 7, 32, 256, 1, 18, 3><<<444, 256, SM3>>>(x, out, 960, 86016, 7282);
}